// round 15
// baseline (speedup 1.0000x reference)
#include <cuda_runtime.h>
#include <cuda_fp16.h>

// SAG: CSR SpMM neighbor aggregation, deg=16, D=48, fp32 in/out.
//
// R14: five structurally different fp16 gathers all land at 22.6-23.3us
// total -> we sit at the LTS chip byte cap at the DVFS-reduced NAT clock.
// Consolidate on the best measured config (R7: 2 nodes/warp, LDG.64 on
// unpadded 96B rows, branch-free clamp, fp16 two-tree, 32 regs / occ 85%)
// and trim overheads: convert does 3x float4/thread (400k threads), and
// main's output stores use __stcs (write-once data, evict-first keeps L2
// ways free for the 16x-reused X scratch). rel_err ~5e-4 < 1e-3.

#define N_CAP   100000
#define D_FEAT  48
#define ROW_I2  12            // 96 B row = 12 int2 (4 halves each)

__device__ __align__(16) __half2 g_Xh[(size_t)N_CAP * 24];   // 9.6 MB scratch

// ---- pre-pass: fp32 [n,48] -> fp16 [n,48]; 3 float4 -> 3 uint2 per thread --
__global__ void convert_kernel(const float4* __restrict__ X4, int total4)
{
    const int t = (blockIdx.x * blockDim.x + threadIdx.x) * 3;  // first float4
    uint2* __restrict__ S2 = reinterpret_cast<uint2*>(g_Xh);
    #pragma unroll
    for (int k = 0; k < 3; ++k) {
        const int i = t + k;
        if (i < total4) {
            const float4 f = __ldg(X4 + i);
            const __half2 a = __floats2half2_rn(f.x, f.y);
            const __half2 b = __floats2half2_rn(f.z, f.w);
            uint2 v;
            v.x = *reinterpret_cast<const unsigned int*>(&a);
            v.y = *reinterpret_cast<const unsigned int*>(&b);
            S2[i] = v;
        }
    }
}

// ---- main: 2 nodes/warp, 16 lanes/node, branch-free fp16 two-tree sum ------
__global__ __launch_bounds__(256, 8)
void sag_fp16_kernel(const int* __restrict__ row_pointers,
                     const int* __restrict__ column_index,
                     float* __restrict__ out,
                     int n_nodes)
{
    const int sub  = threadIdx.x & 15;                  // lane within node group
    const int node = ((blockIdx.x * blockDim.x + threadIdx.x) >> 4);
    if (node >= n_nodes) return;

    const int base = row_pointers[node];
    const int deg  = row_pointers[node + 1] - base;

    // sub-lane e holds edge e's neighbor index (coalesced)
    int my_idx = 0;
    if (sub < deg) my_idx = column_index[base + sub];

    // Lanes 12-15 duplicate lane 11's slot: same cache lines, zero extra
    // traffic, results discarded at store time. Keeps the loop branch-free.
    const int subc = (sub < ROW_I2) ? sub : (ROW_I2 - 1);
    const int2* __restrict__ Xi2 = reinterpret_cast<const int2*>(g_Xh);

    if (deg == 16) {
        // Two independent fp16 trees (edges 0-7, 8-15) combined in fp32.
        __half2 t0a = __float2half2_rn(0.f), t0b = __float2half2_rn(0.f);
        __half2 t1a = __float2half2_rn(0.f), t1b = __float2half2_rn(0.f);

        #pragma unroll
        for (int e = 0; e < 16; ++e) {
            const int idx = __shfl_sync(0xffffffffu, my_idx, e, 16);
            const int2 v = __ldg(Xi2 + (idx * ROW_I2 + subc));
            const __half2 h0 = *reinterpret_cast<const __half2*>(&v.x);
            const __half2 h1 = *reinterpret_cast<const __half2*>(&v.y);
            if (e < 8) { t0a = __hadd2(t0a, h0); t0b = __hadd2(t0b, h1); }
            else       { t1a = __hadd2(t1a, h0); t1b = __hadd2(t1b, h1); }
        }

        if (sub < ROW_I2) {
            const float2 f0 = __half22float2(t0a);
            const float2 f1 = __half22float2(t0b);
            const float2 g0 = __half22float2(t1a);
            const float2 g1 = __half22float2(t1b);
            // Streaming store: out is write-once, never re-read.
            __stcs(reinterpret_cast<float4*>(out) + node * ROW_I2 + sub,
                   make_float4(f0.x + g0.x, f0.y + g0.y, f1.x + g1.x, f1.y + g1.y));
        }
    } else {
        // Generic fallback (never taken here): fp32 accumulate.
        float a0 = 0.f, a1 = 0.f, a2 = 0.f, a3 = 0.f;
        for (int e = 0; e < deg; ++e) {
            int idx = (e < 16) ? __shfl_sync(0xffffffffu, my_idx, e, 16)
                               : column_index[base + e];
            const int2 v = __ldg(Xi2 + (idx * ROW_I2 + subc));
            const float2 f0 = __half22float2(*reinterpret_cast<const __half2*>(&v.x));
            const float2 f1 = __half22float2(*reinterpret_cast<const __half2*>(&v.y));
            a0 += f0.x; a1 += f0.y; a2 += f1.x; a3 += f1.y;
        }
        if (sub < ROW_I2) {
            __stcs(reinterpret_cast<float4*>(out) + node * ROW_I2 + sub,
                   make_float4(a0, a1, a2, a3));
        }
    }
}

// ---- fp32 fallback (only if n exceeds scratch capacity) --------------------
__global__ __launch_bounds__(256, 8)
void sag_fp32_kernel(const float* __restrict__ X,
                     const int* __restrict__ row_pointers,
                     const int* __restrict__ column_index,
                     float* __restrict__ out,
                     int n_nodes)
{
    const int tid  = blockIdx.x * blockDim.x + threadIdx.x;
    const int node = tid >> 4;
    const int lane = tid & 15;
    if (node >= n_nodes) return;

    const int base = row_pointers[node];
    const int deg  = row_pointers[node + 1] - base;
    int my_idx = 0;
    if (lane < deg) my_idx = column_index[base + lane];

    float a0 = 0.f, a1 = 0.f, a2 = 0.f;
    for (int e = 0; e < deg; ++e) {
        int idx = (e < 16) ? __shfl_sync(0xffffffffu, my_idx, e, 16)
                           : column_index[base + e];
        const float* row = X + (size_t)idx * D_FEAT;
        a0 += __ldg(row + lane);
        a1 += __ldg(row + lane + 16);
        a2 += __ldg(row + lane + 32);
    }
    float* orow = out + (size_t)node * D_FEAT;
    orow[lane] = a0; orow[lane + 16] = a1; orow[lane + 32] = a2;
}

extern "C" void kernel_launch(void* const* d_in, const int* in_sizes, int n_in,
                              void* d_out, int out_size)
{
    const float* X   = (const float*)d_in[0];
    const int*   rp  = (const int*)d_in[1];
    const int*   col = (const int*)d_in[2];
    float*       out = (float*)d_out;

    const int n_nodes = in_sizes[1] - 1;

    if (n_nodes <= N_CAP) {
        {
            const int total4  = n_nodes * (D_FEAT / 4);     // 1.2M float4
            const int threads = 256;
            const int workers = (total4 + 2) / 3;           // 3 float4 each
            convert_kernel<<<(workers + threads - 1) / threads, threads>>>(
                reinterpret_cast<const float4*>(X), total4);
        }
        {
            const int threads = 256;                         // 16 nodes / block
            const int blocks = (n_nodes + 15) / 16;
            sag_fp16_kernel<<<blocks, threads>>>(rp, col, out, n_nodes);
        }
    } else {
        const int threads = 256;
        const int blocks = (n_nodes * 16 + threads - 1) / threads;
        sag_fp32_kernel<<<blocks, threads>>>(X, rp, col, out, n_nodes);
    }
}

// round 16
// speedup vs baseline: 1.5466x; 1.5466x over previous
#include <cuda_runtime.h>
#include <cuda_fp16.h>

// SAG: CSR SpMM neighbor aggregation, deg=16, D=48, fp32 in/out.
//
// R15: R14's two trims both regressed (__stcs serialized stores in L1tex;
// 3x-per-thread convert broke coalescing) -> revert to the exact R7 body
// (best measured: main 19.6us). Remaining serialized non-memory time is the
// convert ramp/tail + the inter-kernel launch gap: fuse both phases into ONE
// persistent kernel sized to guaranteed residency (occupancy query x SM
// count), with a replay-safe sense-reversal grid barrier between convert and
// gather. fp16 two-tree accumulation, rel_err ~5e-4 < 1e-3.

#define N_CAP   100000
#define D_FEAT  48
#define ROW_I2  12            // 96 B row = 12 int2 (4 halves each)

__device__ __align__(16) __half2 g_Xh[(size_t)N_CAP * 24];   // 9.6 MB scratch
__device__ unsigned g_bar_cnt = 0;   // returns to 0 every launch -> replay-safe
__device__ unsigned g_bar_gen = 0;   // monotonically grows across replays

__device__ __forceinline__ void grid_barrier(int nblocks)
{
    __syncthreads();
    if (threadIdx.x == 0) {
        __threadfence();                                   // phase-1 writes visible
        const unsigned gen = *(volatile unsigned*)&g_bar_gen;
        if (atomicAdd(&g_bar_cnt, 1u) == (unsigned)nblocks - 1u) {
            g_bar_cnt = 0;
            __threadfence();
            atomicAdd(&g_bar_gen, 1u);                     // release
        } else {
            while (*(volatile unsigned*)&g_bar_gen == gen) { }
        }
    }
    __syncthreads();
}

// ---- fused persistent kernel: convert -> barrier -> gather ----------------
__global__ __launch_bounds__(256, 8)
void sag_fused_kernel(const float4* __restrict__ X4,
                      const int* __restrict__ row_pointers,
                      const int* __restrict__ column_index,
                      float* __restrict__ out,
                      int n_nodes, int nblocks)
{
    // ---- phase 1: fp32 [n,48] -> fp16 [n,48], grid-strided, coalesced ----
    {
        const int total4 = n_nodes * (D_FEAT / 4);
        uint2* __restrict__ S2 = reinterpret_cast<uint2*>(g_Xh);
        for (int i = blockIdx.x * blockDim.x + threadIdx.x; i < total4;
             i += nblocks * blockDim.x) {
            const float4 f = __ldg(X4 + i);
            const __half2 a = __floats2half2_rn(f.x, f.y);
            const __half2 b = __floats2half2_rn(f.z, f.w);
            uint2 v;
            v.x = *reinterpret_cast<const unsigned int*>(&a);
            v.y = *reinterpret_cast<const unsigned int*>(&b);
            S2[i] = v;
        }
    }

    grid_barrier(nblocks);

    // ---- phase 2: persistent node loop, R7 gather body --------------------
    const int sub  = threadIdx.x & 15;                  // lane within node group
    const int nib  = threadIdx.x >> 4;                  // node-slot in block: 0..15
    const int subc = (sub < ROW_I2) ? sub : (ROW_I2 - 1);   // branch-free clamp
    const int2* __restrict__ Xi2 = reinterpret_cast<const int2*>(g_Xh);

    for (int node0 = blockIdx.x * 16; node0 < n_nodes; node0 += nblocks * 16) {
        const int node = node0 + nib;
        if (node < n_nodes) {
            const int base = row_pointers[node];
            const int deg  = row_pointers[node + 1] - base;

            int my_idx = 0;
            if (sub < deg) my_idx = column_index[base + sub];

            if (deg == 16) {
                // Two independent fp16 trees (edges 0-7, 8-15), fp32 combine.
                __half2 t0a = __float2half2_rn(0.f), t0b = __float2half2_rn(0.f);
                __half2 t1a = __float2half2_rn(0.f), t1b = __float2half2_rn(0.f);

                #pragma unroll
                for (int e = 0; e < 16; ++e) {
                    const int idx = __shfl_sync(0xffffffffu, my_idx, e, 16);
                    const int2 v = __ldg(Xi2 + (idx * ROW_I2 + subc));
                    const __half2 h0 = *reinterpret_cast<const __half2*>(&v.x);
                    const __half2 h1 = *reinterpret_cast<const __half2*>(&v.y);
                    if (e < 8) { t0a = __hadd2(t0a, h0); t0b = __hadd2(t0b, h1); }
                    else       { t1a = __hadd2(t1a, h0); t1b = __hadd2(t1b, h1); }
                }

                if (sub < ROW_I2) {
                    const float2 f0 = __half22float2(t0a);
                    const float2 f1 = __half22float2(t0b);
                    const float2 g0 = __half22float2(t1a);
                    const float2 g1 = __half22float2(t1b);
                    reinterpret_cast<float4*>(out)[node * ROW_I2 + sub] =
                        make_float4(f0.x + g0.x, f0.y + g0.y,
                                    f1.x + g1.x, f1.y + g1.y);
                }
            } else {
                // Generic fallback (never taken here): fp32 accumulate.
                float a0 = 0.f, a1 = 0.f, a2 = 0.f, a3 = 0.f;
                for (int e = 0; e < deg; ++e) {
                    int idx = (e < 16) ? __shfl_sync(0xffffffffu, my_idx, e, 16)
                                       : column_index[base + e];
                    const int2 v = __ldg(Xi2 + (idx * ROW_I2 + subc));
                    const float2 f0 = __half22float2(*reinterpret_cast<const __half2*>(&v.x));
                    const float2 f1 = __half22float2(*reinterpret_cast<const __half2*>(&v.y));
                    a0 += f0.x; a1 += f0.y; a2 += f1.x; a3 += f1.y;
                }
                if (sub < ROW_I2) {
                    reinterpret_cast<float4*>(out)[node * ROW_I2 + sub] =
                        make_float4(a0, a1, a2, a3);
                }
            }
        }
    }
}

// ---- fp32 fallback (only if n exceeds scratch capacity) --------------------
__global__ __launch_bounds__(256, 8)
void sag_fp32_kernel(const float* __restrict__ X,
                     const int* __restrict__ row_pointers,
                     const int* __restrict__ column_index,
                     float* __restrict__ out,
                     int n_nodes)
{
    const int tid  = blockIdx.x * blockDim.x + threadIdx.x;
    const int node = tid >> 4;
    const int lane = tid & 15;
    if (node >= n_nodes) return;

    const int base = row_pointers[node];
    const int deg  = row_pointers[node + 1] - base;
    int my_idx = 0;
    if (lane < deg) my_idx = column_index[base + lane];

    float a0 = 0.f, a1 = 0.f, a2 = 0.f;
    for (int e = 0; e < deg; ++e) {
        int idx = (e < 16) ? __shfl_sync(0xffffffffu, my_idx, e, 16)
                           : column_index[base + e];
        const float* row = X + (size_t)idx * D_FEAT;
        a0 += __ldg(row + lane);
        a1 += __ldg(row + lane + 16);
        a2 += __ldg(row + lane + 32);
    }
    float* orow = out + (size_t)node * D_FEAT;
    orow[lane] = a0; orow[lane + 16] = a1; orow[lane + 32] = a2;
}

extern "C" void kernel_launch(void* const* d_in, const int* in_sizes, int n_in,
                              void* d_out, int out_size)
{
    const float* X   = (const float*)d_in[0];
    const int*   rp  = (const int*)d_in[1];
    const int*   col = (const int*)d_in[2];
    float*       out = (float*)d_out;

    const int n_nodes = in_sizes[1] - 1;

    if (n_nodes <= N_CAP) {
        // Guaranteed-resident grid: occupancy x SM count (queried, not assumed).
        int dev = 0, nsm = 0, occ = 0;
        cudaGetDevice(&dev);
        cudaDeviceGetAttribute(&nsm, cudaDevAttrMultiProcessorCount, dev);
        cudaOccupancyMaxActiveBlocksPerMultiprocessor(&occ, sag_fused_kernel, 256, 0);
        if (occ < 1) occ = 1;
        int nblocks = nsm * occ;
        const int work_blocks = (n_nodes + 15) / 16;
        if (nblocks > work_blocks) nblocks = work_blocks;
        if (nblocks < 1) nblocks = 1;

        sag_fused_kernel<<<nblocks, 256>>>(
            reinterpret_cast<const float4*>(X), rp, col, out, n_nodes, nblocks);
    } else {
        const int threads = 256;
        const int blocks = (n_nodes * 16 + threads - 1) / threads;
        sag_fp32_kernel<<<blocks, threads>>>(X, rp, col, out, n_nodes);
    }
}

// round 17
// speedup vs baseline: 1.6474x; 1.0652x over previous
#include <cuda_runtime.h>
#include <cuda_fp16.h>

// SAG: CSR SpMM neighbor aggregation, deg=16, D=48, fp32 in/out.
//
// R16: decouple the two knobs previous rounds conflated.
//   - Sector minimum: UNPADDED 96B fp16 rows; 96 % 32 == 0 so every row is
//     32B-aligned -> exactly 3 sectors/edge (R7's layout).
//   - MIO economy: R13's request structure -- 4 nodes/warp, 8 lanes/node,
//     lanes 0-5 LDG.128 one int4 of the row (lanes 6-7 clamp-duplicate slot 5,
//     same sector, no extra bytes) -> 0.5 MIO-ops/edge (SHFL+LDG share the
//     MIO queue; R7 burned half its LDG issue bandwidth on shuffles).
// fp16 two-tree accumulation (rel_err ~5e-4 < 1e-3), 32 regs, occ ~85%.

#define N_CAP   100000
#define D_FEAT  48
#define ROW_I4  6             // 96 B row = 6 int4 (8 halves each)

__device__ __align__(16) __half2 g_Xh[(size_t)N_CAP * 24];   // 9.6 MB scratch

// ---- pre-pass: fp32 [n,48] -> fp16 [n,48] (contiguous, vectorized) ---------
__global__ void convert_kernel(const float4* __restrict__ X4, int total4)
{
    int t = blockIdx.x * blockDim.x + threadIdx.x;   // one float4 -> one uint2
    if (t >= total4) return;
    const float4 f = __ldg(X4 + t);
    const __half2 a = __floats2half2_rn(f.x, f.y);
    const __half2 b = __floats2half2_rn(f.z, f.w);
    uint2 v;
    v.x = *reinterpret_cast<const unsigned int*>(&a);
    v.y = *reinterpret_cast<const unsigned int*>(&b);
    reinterpret_cast<uint2*>(g_Xh)[t] = v;
}

// ---- main: 4 nodes/warp, 8 lanes/node, LDG.128 on unpadded 96B rows --------
__global__ __launch_bounds__(256, 8)
void sag_fp16_kernel(const int* __restrict__ row_pointers,
                     const int* __restrict__ column_index,
                     float* __restrict__ out,
                     int n_nodes)
{
    const int lane8 = threadIdx.x & 7;                   // lane within node group
    const int node  = (blockIdx.x * blockDim.x + threadIdx.x) >> 3;
    if (node >= n_nodes) return;

    const int base = row_pointers[node];
    const int deg  = row_pointers[node + 1] - base;

    // Clamp lanes 6,7 to slot 5: same 16B (same sector), results discarded.
    const int lc = (lane8 < ROW_I4) ? lane8 : (ROW_I4 - 1);
    const int4* __restrict__ X4 = reinterpret_cast<const int4*>(g_Xh);

    if (deg == 16) {
        // lane8 l holds edge indices (2l, 2l+1) as one int2 (coalesced 64B/group)
        const int2 ip = *reinterpret_cast<const int2*>(column_index + base + 2 * lane8);

        // Two independent fp16 trees (edges 0-7, 8-15), 4 half2 each.
        __half2 t0[4], t1[4];
        #pragma unroll
        for (int k = 0; k < 4; ++k) {
            t0[k] = __float2half2_rn(0.f);
            t1[k] = __float2half2_rn(0.f);
        }

        #pragma unroll
        for (int e = 0; e < 16; ++e) {
            const int idx = __shfl_sync(0xffffffffu, (e & 1) ? ip.y : ip.x, e >> 1, 8);
            const int4 v = __ldg(X4 + (idx * ROW_I4 + lc));     // 16B of 96B row
            const __half2 h0 = *reinterpret_cast<const __half2*>(&v.x);
            const __half2 h1 = *reinterpret_cast<const __half2*>(&v.y);
            const __half2 h2 = *reinterpret_cast<const __half2*>(&v.z);
            const __half2 h3 = *reinterpret_cast<const __half2*>(&v.w);
            if (e < 8) {
                t0[0] = __hadd2(t0[0], h0); t0[1] = __hadd2(t0[1], h1);
                t0[2] = __hadd2(t0[2], h2); t0[3] = __hadd2(t0[3], h3);
            } else {
                t1[0] = __hadd2(t1[0], h0); t1[1] = __hadd2(t1[1], h1);
                t1[2] = __hadd2(t1[2], h2); t1[3] = __hadd2(t1[3], h3);
            }
        }

        // lane8 owns features [8*lane8, 8*lane8+8); lanes 6,7 are duplicates.
        if (lane8 < ROW_I4) {
            float f[8];
            #pragma unroll
            for (int k = 0; k < 4; ++k) {
                const float2 a = __half22float2(t0[k]);
                const float2 b = __half22float2(t1[k]);
                f[2 * k]     = a.x + b.x;
                f[2 * k + 1] = a.y + b.y;
            }
            float4* orow = reinterpret_cast<float4*>(out) + node * 12 + 2 * lane8;
            orow[0] = make_float4(f[0], f[1], f[2], f[3]);
            orow[1] = make_float4(f[4], f[5], f[6], f[7]);
        }
    } else {
        // Generic fallback (never taken here): scalar per-edge accumulate.
        float f[8] = {0.f, 0.f, 0.f, 0.f, 0.f, 0.f, 0.f, 0.f};
        for (int e = 0; e < deg; ++e) {
            const int idx = column_index[base + e];
            const int4 v = __ldg(X4 + (idx * ROW_I4 + lc));
            const __half2* h = reinterpret_cast<const __half2*>(&v);
            #pragma unroll
            for (int k = 0; k < 4; ++k) {
                const float2 a = __half22float2(h[k]);
                f[2 * k] += a.x; f[2 * k + 1] += a.y;
            }
        }
        if (lane8 < ROW_I4) {
            float4* orow = reinterpret_cast<float4*>(out) + node * 12 + 2 * lane8;
            orow[0] = make_float4(f[0], f[1], f[2], f[3]);
            orow[1] = make_float4(f[4], f[5], f[6], f[7]);
        }
    }
}

// ---- fp32 fallback (only if n exceeds scratch capacity) --------------------
__global__ __launch_bounds__(256, 8)
void sag_fp32_kernel(const float* __restrict__ X,
                     const int* __restrict__ row_pointers,
                     const int* __restrict__ column_index,
                     float* __restrict__ out,
                     int n_nodes)
{
    const int tid  = blockIdx.x * blockDim.x + threadIdx.x;
    const int node = tid >> 4;
    const int lane = tid & 15;
    if (node >= n_nodes) return;

    const int base = row_pointers[node];
    const int deg  = row_pointers[node + 1] - base;
    int my_idx = 0;
    if (lane < deg) my_idx = column_index[base + lane];

    float a0 = 0.f, a1 = 0.f, a2 = 0.f;
    for (int e = 0; e < deg; ++e) {
        int idx = (e < 16) ? __shfl_sync(0xffffffffu, my_idx, e, 16)
                           : column_index[base + e];
        const float* row = X + (size_t)idx * D_FEAT;
        a0 += __ldg(row + lane);
        a1 += __ldg(row + lane + 16);
        a2 += __ldg(row + lane + 32);
    }
    float* orow = out + (size_t)node * D_FEAT;
    orow[lane] = a0; orow[lane + 16] = a1; orow[lane + 32] = a2;
}

extern "C" void kernel_launch(void* const* d_in, const int* in_sizes, int n_in,
                              void* d_out, int out_size)
{
    const float* X   = (const float*)d_in[0];
    const int*   rp  = (const int*)d_in[1];
    const int*   col = (const int*)d_in[2];
    float*       out = (float*)d_out;

    const int n_nodes = in_sizes[1] - 1;

    if (n_nodes <= N_CAP) {
        {
            const int total4 = n_nodes * (D_FEAT / 4);      // 1.2M float4
            const int threads = 256;
            convert_kernel<<<(total4 + threads - 1) / threads, threads>>>(
                reinterpret_cast<const float4*>(X), total4);
        }
        {
            const int threads = 256;                         // 32 nodes / block
            const int blocks = (n_nodes + 31) / 32;
            sag_fp16_kernel<<<blocks, threads>>>(rp, col, out, n_nodes);
        }
    } else {
        const int threads = 256;
        const int blocks = (n_nodes * 16 + threads - 1) / threads;
        sag_fp32_kernel<<<blocks, threads>>>(X, rp, col, out, n_nodes);
    }
}